// round 13
// baseline (speedup 1.0000x reference)
#include <cuda_runtime.h>
#include <cuda_fp16.h>
#include <math.h>
#include <stdint.h>

#define NQ 8192
#define NC 8192
#define DIM 256

// Screen image (hi only): per (ntile 0..31, kchunk 0..7) 1024 uint4 (16KB).
// uint4 at [n*4 + (s ^ ((n>>1)&3))] comps c: H2 of k_local = 2s + 8c.
__device__ uint4 g_ehi_img[32 * 8 * 1024];     // 4 MB
// Rescore image (hi+lo): per (ntile, kchunk) 2048 uint4 (32KB).
__device__ uint4 g_esplit[32 * 8 * 2048];      // 8 MB
__device__ float g_enorm[NC];
__device__ int   g_counts[NC];
__device__ float g_partial[NQ];
__device__ float g_sbv[2 * NQ];                // screen per-strip best
__device__ float g_ssv[2 * NQ];                // screen per-strip second
__device__ int   g_sbi[2 * NQ];
__device__ int   g_outidx[NQ];
__device__ float g_xn2[NQ];
__device__ float g_xl2[NQ];
__device__ int   g_maxEl2 = 0;
__device__ int   g_flagq[NQ];
__device__ int   g_flagslot[NQ];
__device__ int   g_flagcount;
__device__ float g_rbv[32 * NQ];
__device__ int   g_rbi[32 * NQ];

#define SC_ES_U4 4096                          // screen: X img 4096 u4 (64KB)
#define SC_STAGE_U4 1024                       // 16KB per stage
#define SC_SMEM ((4096 + 4 * 1024) * 16)       // 131072 B (4-stage ring)
#define RS_ES_U4 8192
#define RS_STAGE_U4 2048
#define RS_SMEM ((8192 + 3 * 2048) * 16)       // 229376 B

// ---------------------------------------------------------------------------
__device__ __forceinline__ void mma16(float* c, uint32_t a0, uint32_t a1,
                                      uint32_t a2, uint32_t a3,
                                      uint32_t b0, uint32_t b1) {
    asm volatile(
        "mma.sync.aligned.m16n8k16.row.col.f32.f16.f16.f32 "
        "{%0,%1,%2,%3}, {%4,%5,%6,%7}, {%8,%9}, {%0,%1,%2,%3};"
        : "+f"(c[0]), "+f"(c[1]), "+f"(c[2]), "+f"(c[3])
        : "r"(a0), "r"(a1), "r"(a2), "r"(a3), "r"(b0), "r"(b1));
}

__device__ __forceinline__ uint32_t pack_h2(float v0, float v1) {
    __half2 h = __halves2half2(__float2half_rn(v0), __float2half_rn(v1));
    return *(uint32_t*)&h;
}
__device__ __forceinline__ void split_h2(float v0, float v1,
                                         uint32_t& hi2, uint32_t& lo2) {
    __half h0 = __float2half_rn(v0);
    __half h1 = __float2half_rn(v1);
    __half l0 = __float2half_rn(v0 - __half2float(h0));
    __half l1 = __float2half_rn(v1 - __half2float(h1));
    __half2 hh = __halves2half2(h0, h1);
    __half2 ll = __halves2half2(l0, l1);
    hi2 = *(uint32_t*)&hh;
    lo2 = *(uint32_t*)&ll;
}
__device__ __forceinline__ void split_acc(float v0, float v1,
                                          uint32_t& hi2, uint32_t& lo2, float& lacc) {
    __half h0 = __float2half_rn(v0);
    __half h1 = __float2half_rn(v1);
    float l0 = v0 - __half2float(h0);
    float l1 = v1 - __half2float(h1);
    lacc += l0 * l0 + l1 * l1;
    __half2 hh = __halves2half2(h0, h1);
    __half2 ll = __halves2half2(__float2half_rn(l0), __float2half_rn(l1));
    hi2 = *(uint32_t*)&hh;
    lo2 = *(uint32_t*)&ll;
}
__device__ __forceinline__ void cp16(uint32_t daddr, const void* src) {
    asm volatile("cp.async.cg.shared.global [%0], [%1], 16;" :: "r"(daddr), "l"(src));
}
__device__ __forceinline__ uint32_t smem_u32(const void* p) {
    uint32_t a;
    asm("{ .reg .u64 t; cvta.to.shared.u64 t, %1; cvt.u32.u64 %0, t; }" : "=r"(a) : "l"(p));
    return a;
}

// ---------------------------------------------------------------------------
// k_split: grid (256, 2) x 256. Warp-per-row (4 rows/warp), shfl reduce.
// ---------------------------------------------------------------------------
__global__ void k_split(const float* __restrict__ X, const float* __restrict__ E) {
    const int t = threadIdx.x;
    const int lane = t & 31;
    const int w = t >> 5;
    const int row0 = blockIdx.x * 32 + w * 4;
    const bool isE = (blockIdx.y == 0);
    const float* src = isE ? E : X;

    if (!isE) {
        if (t < 32) g_counts[blockIdx.x * 32 + t] = 0;
        if (blockIdx.x == 0 && t == 0) g_flagcount = 0;
    }

    #pragma unroll
    for (int rr = 0; rr < 4; rr++) {
        const int r = row0 + rr;
        const float4* p = (const float4*)(src + (size_t)r * DIM);
        float4 a = p[2 * lane];
        float4 b = p[2 * lane + 1];
        float vn = a.x * a.x + a.y * a.y + a.z * a.z + a.w * a.w +
                   b.x * b.x + b.y * b.y + b.z * b.z + b.w * b.w;
        float ln = 0.f;
        uint32_t h2[4], l2[4];
        split_acc(a.x, a.y, h2[0], l2[0], ln);
        split_acc(a.z, a.w, h2[1], l2[1], ln);
        split_acc(b.x, b.y, h2[2], l2[2], ln);
        split_acc(b.z, b.w, h2[3], l2[3], ln);

        if (isE) {
            const int n = r & 255;
            const int ntg = r >> 8;
            #pragma unroll
            for (int i = 0; i < 4; i++) {
                const int P = 4 * lane + i;
                const int kc = P >> 4;
                const int pp16 = P & 15;
                uint32_t* ds = (uint32_t*)&g_ehi_img[(ntg * 8 + kc) * 1024 +
                                n * 4 + ((pp16 & 3) ^ ((n >> 1) & 3))];
                ds[pp16 >> 2] = h2[i];
                const int g16 = (P >> 3) & 1;
                const int pp8 = P & 7;
                uint32_t* dr = (uint32_t*)&g_esplit[(ntg * 8 + kc) * 2048 +
                                n * 8 + ((g16 * 4 + (pp8 & 3)) ^ ((n & 1) << 2))];
                dr[(pp8 >> 2) * 2]     = h2[i];
                dr[(pp8 >> 2) * 2 + 1] = l2[i];
            }
        }
        #pragma unroll
        for (int off = 16; off > 0; off >>= 1) {
            vn += __shfl_down_sync(0xffffffffu, vn, off);
            ln += __shfl_down_sync(0xffffffffu, ln, off);
        }
        if (lane == 0) {
            if (isE) {
                g_enorm[r] = vn;
                atomicMax(&g_maxEl2, __float_as_int(ln));
            } else {
                g_xn2[r] = vn;
                g_xl2[r] = ln;
            }
        }
    }
}

// ---------------------------------------------------------------------------
// k_gemm: 1-pass fp16 screen + fused top-2. Grid (64 q-tiles, 2 strips),
// 256 threads, 8 warps = 2m x 4n (warp tile 64x64). 4-stage cp.async ring.
// ---------------------------------------------------------------------------
__global__ __launch_bounds__(256, 1) void k_gemm(const float* __restrict__ X) {
    extern __shared__ uint4 smem_u4[];

    const int tid   = threadIdx.x;
    const int lane  = tid & 31;
    const int wid   = tid >> 5;
    const int warpm = wid & 1;
    const int warpn = wid >> 1;
    const int gid   = lane >> 2;
    const int tig   = lane & 3;
    const int q0    = blockIdx.x * 128;
    const int strip = blockIdx.y;

    const uint32_t es_base = smem_u32(smem_u4 + SC_ES_U4);
    const uint4* esrc0 = g_ehi_img + (size_t)(strip * 16) * 8 * 1024;

    // prologue: stage chunks 0,1,2
    #pragma unroll
    for (int s = 0; s < 3; s++) {
        #pragma unroll
        for (int j = 0; j < 4; j++)
            cp16(es_base + (uint32_t)(s * SC_STAGE_U4 + tid + j * 256) * 16,
                 esrc0 + s * 1024 + tid + j * 256);
        asm volatile("cp.async.commit_group;" ::: "memory");
    }

    // X tile -> hi-fp16 image (overlaps cp.async)
    #pragma unroll
    for (int i = 0; i < 32; i++) {
        int idx = tid + i * 256;
        int r = idx >> 6;
        int j = idx & 63;
        float4 v = *(const float4*)(X + (size_t)(q0 + r) * DIM + j * 4);
        uint32_t h2a = pack_h2(v.x, v.y);
        uint32_t h2b = pack_h2(v.z, v.w);
        #pragma unroll
        for (int pp = 0; pp < 2; pp++) {
            int P = 2 * j + pp;
            int kc = P >> 4, p = P & 15, s = p & 3, c = p >> 2;
            uint32_t* d =
                (uint32_t*)&smem_u4[kc * 512 + r * 4 + (s ^ ((r >> 1) & 3))];
            d[c] = pp ? h2b : h2a;
        }
    }

    float bestv[8], secv[8];
    int   besti[8];
    #pragma unroll
    for (int i = 0; i < 8; i++) { bestv[i] = INFINITY; secv[i] = INFINITY; besti[i] = 0; }

    const int cbase0 = strip * 4096;

    for (int ct = 0; ct < 16; ct++) {
        float c[4][8][4];
        #pragma unroll
        for (int mt = 0; mt < 4; mt++)
            #pragma unroll
            for (int nt = 0; nt < 8; nt++)
                #pragma unroll
                for (int r = 0; r < 4; r++) c[mt][nt][r] = 0.f;

        for (int kc = 0; kc < 8; kc++) {
            const int cc = ct * 8 + kc;
            asm volatile("cp.async.wait_group 2;" ::: "memory");
            __syncthreads();

            if (cc + 3 < 128) {
                const uint32_t db = es_base + (uint32_t)(((cc + 3) % 4) * SC_STAGE_U4) * 16;
                const uint4* src = esrc0 + (size_t)(cc + 3) * 1024;
                #pragma unroll
                for (int j = 0; j < 4; j++)
                    cp16(db + (uint32_t)(tid + j * 256) * 16, src + tid + j * 256);
            }
            asm volatile("cp.async.commit_group;" ::: "memory");

            const uint4* EsB = smem_u4 + SC_ES_U4 + (cc % 4) * SC_STAGE_U4;
            uint4 A0[4], A1[4];
            #pragma unroll
            for (int mt = 0; mt < 4; mt++) {
                const int r = warpm * 64 + mt * 16 + gid;
                const int sw = tig ^ ((r >> 1) & 3);
                A0[mt] = smem_u4[kc * 512 + r * 4 + sw];
                A1[mt] = smem_u4[kc * 512 + (r + 8) * 4 + sw];
            }
            #pragma unroll
            for (int nt = 0; nt < 8; nt++) {
                const int n = warpn * 64 + nt * 8 + gid;
                uint4 B = EsB[n * 4 + (tig ^ ((n >> 1) & 3))];
                #pragma unroll
                for (int mt = 0; mt < 4; mt++) {
                    mma16(c[mt][nt], A0[mt].x, A1[mt].x, A0[mt].y, A1[mt].y, B.x, B.y);
                    mma16(c[mt][nt], A0[mt].z, A1[mt].z, A0[mt].w, A1[mt].w, B.z, B.w);
                }
            }
        }

        const int cb = cbase0 + ct * 256 + warpn * 64;
        #pragma unroll
        for (int nt = 0; nt < 8; nt++) {
            const int col0 = cb + nt * 8 + tig * 2;
            const float en0 = __ldg(&g_enorm[col0]);
            const float en1 = __ldg(&g_enorm[col0 + 1]);
            #pragma unroll
            for (int mt = 0; mt < 4; mt++) {
                #pragma unroll
                for (int rh = 0; rh < 2; rh++) {
                    const int sl = mt * 2 + rh;
                    float d0 = fmaf(-2.f, c[mt][nt][rh * 2 + 0], en0);
                    float d1 = fmaf(-2.f, c[mt][nt][rh * 2 + 1], en1);
                    if (d0 < secv[sl]) {
                        if (d0 < bestv[sl]) { secv[sl] = bestv[sl]; bestv[sl] = d0; besti[sl] = col0; }
                        else secv[sl] = d0;
                    }
                    if (d1 < secv[sl]) {
                        if (d1 < bestv[sl]) { secv[sl] = bestv[sl]; bestv[sl] = d1; besti[sl] = col0 + 1; }
                        else secv[sl] = d1;
                    }
                }
            }
        }
    }

    __syncthreads();
    float* rv = (float*)(smem_u4 + SC_ES_U4);
    float* sv = rv + 2048;
    int*   ri = (int*)(sv + 2048);
    const int slot16 = warpn * 4 + tig;
    #pragma unroll
    for (int mt = 0; mt < 4; mt++)
        #pragma unroll
        for (int rh = 0; rh < 2; rh++) {
            const int row = warpm * 64 + mt * 16 + rh * 8 + gid;
            rv[row * 16 + slot16] = bestv[mt * 2 + rh];
            sv[row * 16 + slot16] = secv[mt * 2 + rh];
            ri[row * 16 + slot16] = besti[mt * 2 + rh];
        }
    __syncthreads();
    if (tid < 128) {
        float B = rv[tid * 16], S = sv[tid * 16];
        int   I = ri[tid * 16];
        #pragma unroll
        for (int s = 1; s < 16; s++) {
            float b = rv[tid * 16 + s], s2 = sv[tid * 16 + s];
            int   i = ri[tid * 16 + s];
            float newS = fminf(fmaxf(B, b), fminf(S, s2));
            if (b < B || (b == B && i < I)) { B = b; I = i; }
            S = newS;
        }
        g_sbv[strip * NQ + q0 + tid] = B;
        g_ssv[strip * NQ + q0 + tid] = S;
        g_sbi[strip * NQ + q0 + tid] = I;
    }
}

// ---------------------------------------------------------------------------
// k_flag: combine 2 strips; sound certainty test.
// ---------------------------------------------------------------------------
__global__ void k_flag() {
    const int n = blockIdx.x * 256 + threadIdx.x;
    float b0 = g_sbv[n], b1 = g_sbv[NQ + n];
    float s0 = g_ssv[n], s1 = g_ssv[NQ + n];
    int   i0 = g_sbi[n], i1 = g_sbi[NQ + n];
    float gb;
    int gbi;
    if (b1 < b0 || (b1 == b0 && i1 < i0)) { gb = b1; gbi = i1; }
    else                                  { gb = b0; gbi = i0; }
    float gs = fminf(fminf(s0, s1), fmaxf(b0, b1));
    g_outidx[n] = gbi;

    const float maxEl = sqrtf(__int_as_float(g_maxEl2)) * 1.0001f;
    const float xn = sqrtf(g_xn2[n]);
    const float xl = sqrtf(g_xl2[n]) * 1.0001f;
    const float doterr = xl * (1.0f + maxEl + 1e-5f) + (xn + xl) * maxEl + 3e-4f;
    if (gs - gb <= 4.f * doterr) {
        int s = atomicAdd(&g_flagcount, 1);
        g_flagq[s] = n;
        g_flagslot[n] = s;
    } else {
        g_flagslot[n] = -1;
    }
}

// ---------------------------------------------------------------------------
// k_rescore: exact 3-pass fp16-split GEMM, code-parallel (validated, unchanged).
// ---------------------------------------------------------------------------
__global__ __launch_bounds__(256, 1) void k_rescore(const float* __restrict__ X) {
    const int nf = g_flagcount;
    const int qt = blockIdx.x;
    if (qt * 128 >= nf) return;

    extern __shared__ uint4 smem_u4[];
    const int tid   = threadIdx.x;
    const int lane  = tid & 31;
    const int wid   = tid >> 5;
    const int warpm = wid & 1;
    const int warpn = wid >> 1;
    const int gid   = lane >> 2;
    const int tig   = lane & 3;
    const int ntile = blockIdx.y;
    const int ro    = gid & 1;

    const uint32_t es_base = smem_u32(smem_u4 + RS_ES_U4);
    const uint4* esrc0 = g_esplit + (size_t)ntile * 8 * 2048;

    #pragma unroll
    for (int j = 0; j < 8; j++)
        cp16(es_base + (uint32_t)(tid + j * 256) * 16, esrc0 + tid + j * 256);
    asm volatile("cp.async.commit_group;" ::: "memory");
    #pragma unroll
    for (int j = 0; j < 8; j++)
        cp16(es_base + (uint32_t)(RS_STAGE_U4 + tid + j * 256) * 16,
             esrc0 + 2048 + tid + j * 256);
    asm volatile("cp.async.commit_group;" ::: "memory");

    #pragma unroll
    for (int i = 0; i < 32; i++) {
        int idx = tid + i * 256;
        int r = idx >> 6;
        int j = idx & 63;
        int slot = qt * 128 + r;
        int qrow = g_flagq[min(slot, nf - 1)];
        float4 v = *(const float4*)(X + (size_t)qrow * DIM + j * 4);
        int g16 = j >> 2;
        int p0  = (j & 3) * 2;
        int tg0 = p0 & 3;
        int h8  = p0 >> 2;
        int rsw = (r & 1) << 2;
        uint32_t h2a, l2a, h2b, l2b;
        split_h2(v.x, v.y, h2a, l2a);
        split_h2(v.z, v.w, h2b, l2b);
        uint32_t* d0 = (uint32_t*)&smem_u4[r * 64 + ((g16 * 4 + tg0) ^ rsw)];
        uint32_t* d1 = (uint32_t*)&smem_u4[r * 64 + ((g16 * 4 + tg0 + 1) ^ rsw)];
        d0[h8 * 2] = h2a;  d0[h8 * 2 + 1] = l2a;
        d1[h8 * 2] = h2b;  d1[h8 * 2 + 1] = l2b;
    }

    float best[8];
    int   bidx[8];
    #pragma unroll
    for (int i = 0; i < 8; i++) { best[i] = INFINITY; bidx[i] = 0; }

    float c[4][8][4];
    #pragma unroll
    for (int mt = 0; mt < 4; mt++)
        #pragma unroll
        for (int nt = 0; nt < 8; nt++)
            #pragma unroll
            for (int r = 0; r < 4; r++) c[mt][nt][r] = 0.f;

    for (int kc = 0; kc < 8; kc++) {
        asm volatile("cp.async.wait_group 1;" ::: "memory");
        __syncthreads();

        if (kc + 2 < 8) {
            const uint32_t db = es_base + (uint32_t)(((kc + 2) % 3) * RS_STAGE_U4) * 16;
            const uint4* src = esrc0 + (size_t)(kc + 2) * 2048;
            #pragma unroll
            for (int j = 0; j < 8; j++)
                cp16(db + (uint32_t)(tid + j * 256) * 16, src + tid + j * 256);
        }
        asm volatile("cp.async.commit_group;" ::: "memory");

        const uint4* EsB = smem_u4 + RS_ES_U4 + (kc % 3) * RS_STAGE_U4;
        #pragma unroll
        for (int gg = 0; gg < 2; gg++) {
            uint4 A0[4], A1[4];
            const int sA = ((2 * kc + gg) * 4 + tig) ^ (ro << 2);
            #pragma unroll
            for (int mt = 0; mt < 4; mt++) {
                const int r = warpm * 64 + mt * 16 + gid;
                A0[mt] = smem_u4[r * 64 + sA];
                A1[mt] = smem_u4[(r + 8) * 64 + sA];
            }
            const int sB = (gg * 4 + tig) ^ (ro << 2);
            #pragma unroll
            for (int nt = 0; nt < 8; nt++) {
                const int n = warpn * 64 + nt * 8 + gid;
                uint4 B = EsB[n * 8 + sB];
                #pragma unroll
                for (int mt = 0; mt < 4; mt++) {
                    mma16(c[mt][nt], A0[mt].x, A1[mt].x, A0[mt].z, A1[mt].z, B.x, B.z);
                    mma16(c[mt][nt], A0[mt].x, A1[mt].x, A0[mt].z, A1[mt].z, B.y, B.w);
                    mma16(c[mt][nt], A0[mt].y, A1[mt].y, A0[mt].w, A1[mt].w, B.x, B.z);
                }
            }
        }
    }

    const int cb = ntile * 256 + warpn * 64;
    #pragma unroll
    for (int nt = 0; nt < 8; nt++) {
        const int col0 = cb + nt * 8 + tig * 2;
        const float en0 = __ldg(&g_enorm[col0]);
        const float en1 = __ldg(&g_enorm[col0 + 1]);
        #pragma unroll
        for (int mt = 0; mt < 4; mt++) {
            float d;
            d = fmaf(-2.f, c[mt][nt][0], en0);
            if (d < best[mt * 2 + 0]) { best[mt * 2 + 0] = d; bidx[mt * 2 + 0] = col0; }
            d = fmaf(-2.f, c[mt][nt][1], en1);
            if (d < best[mt * 2 + 0]) { best[mt * 2 + 0] = d; bidx[mt * 2 + 0] = col0 + 1; }
            d = fmaf(-2.f, c[mt][nt][2], en0);
            if (d < best[mt * 2 + 1]) { best[mt * 2 + 1] = d; bidx[mt * 2 + 1] = col0; }
            d = fmaf(-2.f, c[mt][nt][3], en1);
            if (d < best[mt * 2 + 1]) { best[mt * 2 + 1] = d; bidx[mt * 2 + 1] = col0 + 1; }
        }
    }

    __syncthreads();
    float* rv = (float*)(smem_u4 + RS_ES_U4);
    int*   ri = (int*)(rv + 2048);
    const int slot16 = warpn * 4 + tig;
    #pragma unroll
    for (int mt = 0; mt < 4; mt++)
        #pragma unroll
        for (int rh = 0; rh < 2; rh++) {
            const int row = warpm * 64 + mt * 16 + rh * 8 + gid;
            rv[row * 16 + slot16] = best[mt * 2 + rh];
            ri[row * 16 + slot16] = bidx[mt * 2 + rh];
        }
    __syncthreads();
    if (tid < 128) {
        float bv = rv[tid * 16];
        int   bi = ri[tid * 16];
        #pragma unroll
        for (int s = 1; s < 16; s++) {
            float v = rv[tid * 16 + s];
            int   i = ri[tid * 16 + s];
            if (v < bv || (v == bv && i < bi)) { bv = v; bi = i; }
        }
        g_rbv[ntile * NQ + qt * 128 + tid] = bv;
        g_rbi[ntile * NQ + qt * 128 + tid] = bi;
    }
}

// ---------------------------------------------------------------------------
// k_gather: warp per query row; resolve index, output, loss, histogram.
// ---------------------------------------------------------------------------
__global__ void k_gather(const float* __restrict__ X, const float* __restrict__ E,
                         float* __restrict__ out) {
    const int w = threadIdx.x >> 5;
    const int lane = threadIdx.x & 31;
    const int n = blockIdx.x * 8 + w;
    const int fs = g_flagslot[n];
    int idx;
    if (fs >= 0) {
        float v = g_rbv[lane * NQ + fs];
        int   i = g_rbi[lane * NQ + fs];
        #pragma unroll
        for (int off = 16; off > 0; off >>= 1) {
            float ov = __shfl_down_sync(0xffffffffu, v, off);
            int   oi = __shfl_down_sync(0xffffffffu, i, off);
            if (ov < v || (ov == v && oi < i)) { v = ov; i = oi; }
        }
        idx = __shfl_sync(0xffffffffu, i, 0);
    } else {
        idx = g_outidx[n];
    }

    const float4* qe = (const float4*)(E + (size_t)idx * DIM);
    const float4* xr = (const float4*)(X + (size_t)n * DIM);
    float4* o = (float4*)(out + (size_t)n * DIM);
    float s = 0.f;
    #pragma unroll
    for (int h = 0; h < 2; h++) {
        int j = lane + h * 32;
        float4 q = qe[j], x = xr[j];
        float dx = q.x - x.x, dy = q.y - x.y, dz = q.z - x.z, dw = q.w - x.w;
        float4 r;
        r.x = x.x + dx; r.y = x.y + dy; r.z = x.z + dz; r.w = x.w + dw;
        o[j] = r;
        s += dx * dx + dy * dy + dz * dz + dw * dw;
    }
    #pragma unroll
    for (int off = 16; off > 0; off >>= 1)
        s += __shfl_down_sync(0xffffffffu, s, off);
    if (lane == 0) {
        g_partial[n] = s;
        atomicAdd(&g_counts[idx], 1);
    }
}

// ---------------------------------------------------------------------------
// k_final: deterministic loss + perplexity, warp-shfl reductions.
// ---------------------------------------------------------------------------
__global__ void k_final(float* __restrict__ out, int out_size) {
    __shared__ float wsum[32], wh[32];
    const int t = threadIdx.x;
    const int lane = t & 31;
    const int w = t >> 5;

    float s = 0.f;
    for (int i = t; i < NQ; i += 1024) s += g_partial[i];
    float h = 0.f;
    for (int i = t; i < NC; i += 1024) {
        float p = (float)g_counts[i] * (1.0f / (float)NQ);
        h += p * logf(p + 1e-10f);
    }
    #pragma unroll
    for (int off = 16; off > 0; off >>= 1) {
        s += __shfl_down_sync(0xffffffffu, s, off);
        h += __shfl_down_sync(0xffffffffu, h, off);
    }
    if (lane == 0) { wsum[w] = s; wh[w] = h; }
    __syncthreads();
    if (w == 0) {
        s = wsum[lane];
        h = wh[lane];
        #pragma unroll
        for (int off = 16; off > 0; off >>= 1) {
            s += __shfl_down_sync(0xffffffffu, s, off);
            h += __shfl_down_sync(0xffffffffu, h, off);
        }
        if (lane == 0) {
            float mean_sq = s / (float)((size_t)NQ * DIM);
            float loss = mean_sq + 0.25f * mean_sq;
            float perplexity = expf(-h);
            if (out_size >= NQ * DIM + 2) {
                out[(size_t)NQ * DIM]     = loss;
                out[(size_t)NQ * DIM + 1] = perplexity;
            }
        }
    }
}

// ---------------------------------------------------------------------------
extern "C" void kernel_launch(void* const* d_in, const int* in_sizes, int n_in,
                              void* d_out, int out_size) {
    const float* X = (const float*)d_in[0];   // [32,256,256] -> [8192,256]
    const float* E = (const float*)d_in[1];   // [8192,256]
    float* out = (float*)d_out;

    cudaFuncSetAttribute(k_gemm, cudaFuncAttributeMaxDynamicSharedMemorySize, SC_SMEM);
    cudaFuncSetAttribute(k_rescore, cudaFuncAttributeMaxDynamicSharedMemorySize, RS_SMEM);

    k_split<<<dim3(256, 2), 256>>>(X, E);
    k_gemm<<<dim3(64, 2), 256, SC_SMEM>>>(X);
    k_flag<<<32, 256>>>();
    k_rescore<<<dim3(64, 32), 256, RS_SMEM>>>(X);
    k_gather<<<1024, 256>>>(X, E, out);
    k_final<<<1, 1024>>>(out, out_size);
}

// round 14
// speedup vs baseline: 1.7345x; 1.7345x over previous
#include <cuda_runtime.h>
#include <cuda_fp16.h>
#include <math.h>
#include <stdint.h>

#define NQ 8192
#define NC 8192
#define DIM 256

// Screen image (hi only): per (ntile 0..31, kchunk 0..7) 1024 uint4 (16KB).
// uint4 at [n*4 + (s ^ ((n>>1)&3))] comps c: H2 of k_local = 2s + 8c.
__device__ uint4 g_ehi_img[32 * 8 * 1024];     // 4 MB
// Rescore image (hi+lo): per (ntile, kchunk) 2048 uint4 (32KB).
// uint4 at [n*8 + ((g16*4+tig)^((n&1)<<2))] = {H2(k0),L2(k0),H2(k0+8),L2(k0+8)}.
__device__ uint4 g_esplit[32 * 8 * 2048];      // 8 MB
__device__ float g_enorm[NC];
__device__ int   g_counts[NC];
__device__ float g_partial[NQ];
__device__ float g_sbv[2 * NQ];                // screen per-strip best
__device__ float g_ssv[2 * NQ];                // screen per-strip second
__device__ int   g_sbi[2 * NQ];
__device__ int   g_outidx[NQ];
__device__ float g_xn2[NQ];                    // ||x||^2
__device__ float g_xl2[NQ];                    // ||xl||^2
__device__ int   g_maxEl2 = 0;                 // max ||el||^2 bits (monotone)
__device__ int   g_flagq[NQ];
__device__ int   g_flagslot[NQ];
__device__ int   g_flagcount;
__device__ float g_rbv[32 * NQ];               // rescore best per (code-tile, slot)
__device__ int   g_rbi[32 * NQ];

#define SC_ES_U4 4096                          // screen: X img 4096 u4 (64KB)
#define SC_STAGE_U4 1024
#define SC_SMEM ((4096 + 3 * 1024) * 16)       // 114688 B
#define RS_ES_U4 8192                          // rescore: X img 8192 u4 (128KB)
#define RS_STAGE_U4 2048
#define RS_SMEM ((8192 + 3 * 2048) * 16)       // 229376 B

// ---------------------------------------------------------------------------
__device__ __forceinline__ void mma16(float* c, uint32_t a0, uint32_t a1,
                                      uint32_t a2, uint32_t a3,
                                      uint32_t b0, uint32_t b1) {
    asm volatile(
        "mma.sync.aligned.m16n8k16.row.col.f32.f16.f16.f32 "
        "{%0,%1,%2,%3}, {%4,%5,%6,%7}, {%8,%9}, {%0,%1,%2,%3};"
        : "+f"(c[0]), "+f"(c[1]), "+f"(c[2]), "+f"(c[3])
        : "r"(a0), "r"(a1), "r"(a2), "r"(a3), "r"(b0), "r"(b1));
}

__device__ __forceinline__ uint32_t pack_h2(float v0, float v1) {
    __half2 h = __halves2half2(__float2half_rn(v0), __float2half_rn(v1));
    return *(uint32_t*)&h;
}
__device__ __forceinline__ void split_h2(float v0, float v1,
                                         uint32_t& hi2, uint32_t& lo2) {
    __half h0 = __float2half_rn(v0);
    __half h1 = __float2half_rn(v1);
    __half l0 = __float2half_rn(v0 - __half2float(h0));
    __half l1 = __float2half_rn(v1 - __half2float(h1));
    __half2 hh = __halves2half2(h0, h1);
    __half2 ll = __halves2half2(l0, l1);
    hi2 = *(uint32_t*)&hh;
    lo2 = *(uint32_t*)&ll;
}
__device__ __forceinline__ void split_acc(float v0, float v1,
                                          uint32_t& hi2, uint32_t& lo2, float& lacc) {
    __half h0 = __float2half_rn(v0);
    __half h1 = __float2half_rn(v1);
    float l0 = v0 - __half2float(h0);
    float l1 = v1 - __half2float(h1);
    lacc += l0 * l0 + l1 * l1;
    __half2 hh = __halves2half2(h0, h1);
    __half2 ll = __halves2half2(__float2half_rn(l0), __float2half_rn(l1));
    hi2 = *(uint32_t*)&hh;
    lo2 = *(uint32_t*)&ll;
}
__device__ __forceinline__ void cp16(uint32_t daddr, const void* src) {
    asm volatile("cp.async.cg.shared.global [%0], [%1], 16;" :: "r"(daddr), "l"(src));
}
__device__ __forceinline__ uint32_t smem_u32(const void* p) {
    uint32_t a;
    asm("{ .reg .u64 t; cvta.to.shared.u64 t, %1; cvt.u32.u64 %0, t; }" : "=r"(a) : "l"(p));
    return a;
}

// ---------------------------------------------------------------------------
// k_split: grid (256, 2) x 256. Warp-per-row (4 rows/warp), shfl reduce.
// ---------------------------------------------------------------------------
__global__ void k_split(const float* __restrict__ X, const float* __restrict__ E) {
    const int t = threadIdx.x;
    const int lane = t & 31;
    const int w = t >> 5;
    const int row0 = blockIdx.x * 32 + w * 4;
    const bool isE = (blockIdx.y == 0);
    const float* src = isE ? E : X;

    if (!isE) {
        if (t < 32) g_counts[blockIdx.x * 32 + t] = 0;
        if (blockIdx.x == 0 && t == 0) g_flagcount = 0;
    }

    #pragma unroll
    for (int rr = 0; rr < 4; rr++) {
        const int r = row0 + rr;
        const float4* p = (const float4*)(src + (size_t)r * DIM);
        float4 a = p[2 * lane];
        float4 b = p[2 * lane + 1];
        float vn = a.x * a.x + a.y * a.y + a.z * a.z + a.w * a.w +
                   b.x * b.x + b.y * b.y + b.z * b.z + b.w * b.w;
        float ln = 0.f;
        uint32_t h2[4], l2[4];
        split_acc(a.x, a.y, h2[0], l2[0], ln);
        split_acc(a.z, a.w, h2[1], l2[1], ln);
        split_acc(b.x, b.y, h2[2], l2[2], ln);
        split_acc(b.z, b.w, h2[3], l2[3], ln);

        if (isE) {
            const int n = r & 255;
            const int ntg = r >> 8;
            #pragma unroll
            for (int i = 0; i < 4; i++) {
                const int P = 4 * lane + i;
                const int kc = P >> 4;
                const int pp16 = P & 15;
                uint32_t* ds = (uint32_t*)&g_ehi_img[(ntg * 8 + kc) * 1024 +
                                n * 4 + ((pp16 & 3) ^ ((n >> 1) & 3))];
                ds[pp16 >> 2] = h2[i];
                const int g16 = (P >> 3) & 1;
                const int pp8 = P & 7;
                uint32_t* dr = (uint32_t*)&g_esplit[(ntg * 8 + kc) * 2048 +
                                n * 8 + ((g16 * 4 + (pp8 & 3)) ^ ((n & 1) << 2))];
                dr[(pp8 >> 2) * 2]     = h2[i];
                dr[(pp8 >> 2) * 2 + 1] = l2[i];
            }
        }
        #pragma unroll
        for (int off = 16; off > 0; off >>= 1) {
            vn += __shfl_down_sync(0xffffffffu, vn, off);
            ln += __shfl_down_sync(0xffffffffu, ln, off);
        }
        if (lane == 0) {
            if (isE) {
                g_enorm[r] = vn;
                atomicMax(&g_maxEl2, __float_as_int(ln));
            } else {
                g_xn2[r] = vn;
                g_xl2[r] = ln;
            }
        }
    }
}

// ---------------------------------------------------------------------------
// k_gemm: 1-pass fp16 screen GEMM + fused top-2 (guarded cheap-path update).
// Grid (64 q-tiles, 2 strips) x 256; 8 warps = 2m x 4n (warp tile 64x64).
// ---------------------------------------------------------------------------
__global__ __launch_bounds__(256, 1) void k_gemm(const float* __restrict__ X) {
    extern __shared__ uint4 smem_u4[];

    const int tid   = threadIdx.x;
    const int lane  = tid & 31;
    const int wid   = tid >> 5;
    const int warpm = wid & 1;
    const int warpn = wid >> 1;
    const int gid   = lane >> 2;
    const int tig   = lane & 3;
    const int q0    = blockIdx.x * 128;
    const int strip = blockIdx.y;

    const uint32_t es_base = smem_u32(smem_u4 + SC_ES_U4);
    const uint4* esrc0 = g_ehi_img + (size_t)(strip * 16) * 8 * 1024;

    #pragma unroll
    for (int j = 0; j < 4; j++)
        cp16(es_base + (uint32_t)(tid + j * 256) * 16, esrc0 + tid + j * 256);
    asm volatile("cp.async.commit_group;" ::: "memory");
    #pragma unroll
    for (int j = 0; j < 4; j++)
        cp16(es_base + (uint32_t)(SC_STAGE_U4 + tid + j * 256) * 16,
             esrc0 + 1024 + tid + j * 256);
    asm volatile("cp.async.commit_group;" ::: "memory");

    #pragma unroll
    for (int i = 0; i < 32; i++) {
        int idx = tid + i * 256;
        int r = idx >> 6;
        int j = idx & 63;
        float4 v = *(const float4*)(X + (size_t)(q0 + r) * DIM + j * 4);
        uint32_t h2a = pack_h2(v.x, v.y);
        uint32_t h2b = pack_h2(v.z, v.w);
        #pragma unroll
        for (int pp = 0; pp < 2; pp++) {
            int P = 2 * j + pp;
            int kc = P >> 4, p = P & 15, s = p & 3, c = p >> 2;
            uint32_t* d =
                (uint32_t*)&smem_u4[kc * 512 + r * 4 + (s ^ ((r >> 1) & 3))];
            d[c] = pp ? h2b : h2a;
        }
    }

    float bestv[8], secv[8];
    int   besti[8];
    #pragma unroll
    for (int i = 0; i < 8; i++) { bestv[i] = INFINITY; secv[i] = INFINITY; besti[i] = 0; }

    const int cbase0 = strip * 4096;

    for (int ct = 0; ct < 16; ct++) {
        float c[4][8][4];
        #pragma unroll
        for (int mt = 0; mt < 4; mt++)
            #pragma unroll
            for (int nt = 0; nt < 8; nt++)
                #pragma unroll
                for (int r = 0; r < 4; r++) c[mt][nt][r] = 0.f;

        for (int kc = 0; kc < 8; kc++) {
            const int cc = ct * 8 + kc;
            asm volatile("cp.async.wait_group 1;" ::: "memory");
            __syncthreads();

            if (cc + 2 < 128) {
                const uint32_t db = es_base + (uint32_t)(((cc + 2) % 3) * SC_STAGE_U4) * 16;
                const uint4* src = esrc0 + (size_t)(cc + 2) * 1024;
                #pragma unroll
                for (int j = 0; j < 4; j++)
                    cp16(db + (uint32_t)(tid + j * 256) * 16, src + tid + j * 256);
            }
            asm volatile("cp.async.commit_group;" ::: "memory");

            const uint4* EsB = smem_u4 + SC_ES_U4 + (cc % 3) * SC_STAGE_U4;
            uint4 A0[4], A1[4];
            #pragma unroll
            for (int mt = 0; mt < 4; mt++) {
                const int r = warpm * 64 + mt * 16 + gid;
                const int sw = tig ^ ((r >> 1) & 3);
                A0[mt] = smem_u4[kc * 512 + r * 4 + sw];
                A1[mt] = smem_u4[kc * 512 + (r + 8) * 4 + sw];
            }
            #pragma unroll
            for (int nt = 0; nt < 8; nt++) {
                const int n = warpn * 64 + nt * 8 + gid;
                uint4 B = EsB[n * 4 + (tig ^ ((n >> 1) & 3))];
                #pragma unroll
                for (int mt = 0; mt < 4; mt++) {
                    mma16(c[mt][nt], A0[mt].x, A1[mt].x, A0[mt].y, A1[mt].y, B.x, B.y);
                    mma16(c[mt][nt], A0[mt].z, A1[mt].z, A0[mt].w, A1[mt].w, B.z, B.w);
                }
            }
        }

        const int cb = cbase0 + ct * 256 + warpn * 64;
        #pragma unroll
        for (int nt = 0; nt < 8; nt++) {
            const int col0 = cb + nt * 8 + tig * 2;
            const float en0 = __ldg(&g_enorm[col0]);
            const float en1 = __ldg(&g_enorm[col0 + 1]);
            #pragma unroll
            for (int mt = 0; mt < 4; mt++) {
                #pragma unroll
                for (int rh = 0; rh < 2; rh++) {
                    const int sl = mt * 2 + rh;
                    float d0 = fmaf(-2.f, c[mt][nt][rh * 2 + 0], en0);
                    float d1 = fmaf(-2.f, c[mt][nt][rh * 2 + 1], en1);
                    if (d0 < secv[sl]) {
                        if (d0 < bestv[sl]) { secv[sl] = bestv[sl]; bestv[sl] = d0; besti[sl] = col0; }
                        else secv[sl] = d0;
                    }
                    if (d1 < secv[sl]) {
                        if (d1 < bestv[sl]) { secv[sl] = bestv[sl]; bestv[sl] = d1; besti[sl] = col0 + 1; }
                        else secv[sl] = d1;
                    }
                }
            }
        }
    }

    __syncthreads();
    float* rv = (float*)(smem_u4 + SC_ES_U4);
    float* sv = rv + 2048;
    int*   ri = (int*)(sv + 2048);
    const int slot16 = warpn * 4 + tig;
    #pragma unroll
    for (int mt = 0; mt < 4; mt++)
        #pragma unroll
        for (int rh = 0; rh < 2; rh++) {
            const int row = warpm * 64 + mt * 16 + rh * 8 + gid;
            rv[row * 16 + slot16] = bestv[mt * 2 + rh];
            sv[row * 16 + slot16] = secv[mt * 2 + rh];
            ri[row * 16 + slot16] = besti[mt * 2 + rh];
        }
    __syncthreads();
    if (tid < 128) {
        float B = rv[tid * 16], S = sv[tid * 16];
        int   I = ri[tid * 16];
        #pragma unroll
        for (int s = 1; s < 16; s++) {
            float b = rv[tid * 16 + s], s2 = sv[tid * 16 + s];
            int   i = ri[tid * 16 + s];
            float newS = fminf(fmaxf(B, b), fminf(S, s2));
            if (b < B || (b == B && i < I)) { B = b; I = i; }
            S = newS;
        }
        g_sbv[strip * NQ + q0 + tid] = B;
        g_ssv[strip * NQ + q0 + tid] = S;
        g_sbi[strip * NQ + q0 + tid] = I;
    }
}

// ---------------------------------------------------------------------------
// k_flag: combine strips; sound certainty test with measured residual norms.
// ---------------------------------------------------------------------------
__global__ void k_flag() {
    const int n = blockIdx.x * 256 + threadIdx.x;
    float b0 = g_sbv[n], b1 = g_sbv[NQ + n];
    float s0 = g_ssv[n], s1 = g_ssv[NQ + n];
    int   i0 = g_sbi[n], i1 = g_sbi[NQ + n];
    float gb;
    int gbi;
    if (b1 < b0 || (b1 == b0 && i1 < i0)) { gb = b1; gbi = i1; }
    else                                  { gb = b0; gbi = i0; }
    float gs = fminf(fminf(s0, s1), fmaxf(b0, b1));
    g_outidx[n] = gbi;

    const float maxEl = sqrtf(__int_as_float(g_maxEl2)) * 1.0001f;
    const float xn = sqrtf(g_xn2[n]);
    const float xl = sqrtf(g_xl2[n]) * 1.0001f;
    const float doterr = xl * (1.0f + maxEl + 1e-5f) + (xn + xl) * maxEl + 3e-4f;
    if (gs - gb <= 4.f * doterr) {
        int s = atomicAdd(&g_flagcount, 1);
        g_flagq[s] = n;
        g_flagslot[n] = s;
    } else {
        g_flagslot[n] = -1;
    }
}

// ---------------------------------------------------------------------------
// k_rescore: exact 3-pass fp16-split GEMM over compacted flagged queries,
// code-parallel: grid (64 q-tiles, 32 code-tiles of 256). Early exit.
// ---------------------------------------------------------------------------
__global__ __launch_bounds__(256, 1) void k_rescore(const float* __restrict__ X) {
    const int nf = g_flagcount;
    const int qt = blockIdx.x;
    if (qt * 128 >= nf) return;

    extern __shared__ uint4 smem_u4[];
    const int tid   = threadIdx.x;
    const int lane  = tid & 31;
    const int wid   = tid >> 5;
    const int warpm = wid & 1;
    const int warpn = wid >> 1;
    const int gid   = lane >> 2;
    const int tig   = lane & 3;
    const int ntile = blockIdx.y;
    const int ro    = gid & 1;

    const uint32_t es_base = smem_u32(smem_u4 + RS_ES_U4);
    const uint4* esrc0 = g_esplit + (size_t)ntile * 8 * 2048;

    #pragma unroll
    for (int j = 0; j < 8; j++)
        cp16(es_base + (uint32_t)(tid + j * 256) * 16, esrc0 + tid + j * 256);
    asm volatile("cp.async.commit_group;" ::: "memory");
    #pragma unroll
    for (int j = 0; j < 8; j++)
        cp16(es_base + (uint32_t)(RS_STAGE_U4 + tid + j * 256) * 16,
             esrc0 + 2048 + tid + j * 256);
    asm volatile("cp.async.commit_group;" ::: "memory");

    #pragma unroll
    for (int i = 0; i < 32; i++) {
        int idx = tid + i * 256;
        int r = idx >> 6;
        int j = idx & 63;
        int slot = qt * 128 + r;
        int qrow = g_flagq[min(slot, nf - 1)];
        float4 v = *(const float4*)(X + (size_t)qrow * DIM + j * 4);
        int g16 = j >> 2;
        int p0  = (j & 3) * 2;
        int tg0 = p0 & 3;
        int h8  = p0 >> 2;
        int rsw = (r & 1) << 2;
        uint32_t h2a, l2a, h2b, l2b;
        split_h2(v.x, v.y, h2a, l2a);
        split_h2(v.z, v.w, h2b, l2b);
        uint32_t* d0 = (uint32_t*)&smem_u4[r * 64 + ((g16 * 4 + tg0) ^ rsw)];
        uint32_t* d1 = (uint32_t*)&smem_u4[r * 64 + ((g16 * 4 + tg0 + 1) ^ rsw)];
        d0[h8 * 2] = h2a;  d0[h8 * 2 + 1] = l2a;
        d1[h8 * 2] = h2b;  d1[h8 * 2 + 1] = l2b;
    }

    float best[8];
    int   bidx[8];
    #pragma unroll
    for (int i = 0; i < 8; i++) { best[i] = INFINITY; bidx[i] = 0; }

    float c[4][8][4];
    #pragma unroll
    for (int mt = 0; mt < 4; mt++)
        #pragma unroll
        for (int nt = 0; nt < 8; nt++)
            #pragma unroll
            for (int r = 0; r < 4; r++) c[mt][nt][r] = 0.f;

    for (int kc = 0; kc < 8; kc++) {
        asm volatile("cp.async.wait_group 1;" ::: "memory");
        __syncthreads();

        if (kc + 2 < 8) {
            const uint32_t db = es_base + (uint32_t)(((kc + 2) % 3) * RS_STAGE_U4) * 16;
            const uint4* src = esrc0 + (size_t)(kc + 2) * 2048;
            #pragma unroll
            for (int j = 0; j < 8; j++)
                cp16(db + (uint32_t)(tid + j * 256) * 16, src + tid + j * 256);
        }
        asm volatile("cp.async.commit_group;" ::: "memory");

        const uint4* EsB = smem_u4 + RS_ES_U4 + (kc % 3) * RS_STAGE_U4;
        #pragma unroll
        for (int gg = 0; gg < 2; gg++) {
            uint4 A0[4], A1[4];
            const int sA = ((2 * kc + gg) * 4 + tig) ^ (ro << 2);
            #pragma unroll
            for (int mt = 0; mt < 4; mt++) {
                const int r = warpm * 64 + mt * 16 + gid;
                A0[mt] = smem_u4[r * 64 + sA];
                A1[mt] = smem_u4[(r + 8) * 64 + sA];
            }
            const int sB = (gg * 4 + tig) ^ (ro << 2);
            #pragma unroll
            for (int nt = 0; nt < 8; nt++) {
                const int n = warpn * 64 + nt * 8 + gid;
                uint4 B = EsB[n * 8 + sB];
                #pragma unroll
                for (int mt = 0; mt < 4; mt++) {
                    mma16(c[mt][nt], A0[mt].x, A1[mt].x, A0[mt].z, A1[mt].z, B.x, B.z);
                    mma16(c[mt][nt], A0[mt].x, A1[mt].x, A0[mt].z, A1[mt].z, B.y, B.w);
                    mma16(c[mt][nt], A0[mt].y, A1[mt].y, A0[mt].w, A1[mt].w, B.x, B.z);
                }
            }
        }
    }

    const int cb = ntile * 256 + warpn * 64;
    #pragma unroll
    for (int nt = 0; nt < 8; nt++) {
        const int col0 = cb + nt * 8 + tig * 2;
        const float en0 = __ldg(&g_enorm[col0]);
        const float en1 = __ldg(&g_enorm[col0 + 1]);
        #pragma unroll
        for (int mt = 0; mt < 4; mt++) {
            float d;
            d = fmaf(-2.f, c[mt][nt][0], en0);
            if (d < best[mt * 2 + 0]) { best[mt * 2 + 0] = d; bidx[mt * 2 + 0] = col0; }
            d = fmaf(-2.f, c[mt][nt][1], en1);
            if (d < best[mt * 2 + 0]) { best[mt * 2 + 0] = d; bidx[mt * 2 + 0] = col0 + 1; }
            d = fmaf(-2.f, c[mt][nt][2], en0);
            if (d < best[mt * 2 + 1]) { best[mt * 2 + 1] = d; bidx[mt * 2 + 1] = col0; }
            d = fmaf(-2.f, c[mt][nt][3], en1);
            if (d < best[mt * 2 + 1]) { best[mt * 2 + 1] = d; bidx[mt * 2 + 1] = col0 + 1; }
        }
    }

    __syncthreads();
    float* rv = (float*)(smem_u4 + RS_ES_U4);
    int*   ri = (int*)(rv + 2048);
    const int slot16 = warpn * 4 + tig;
    #pragma unroll
    for (int mt = 0; mt < 4; mt++)
        #pragma unroll
        for (int rh = 0; rh < 2; rh++) {
            const int row = warpm * 64 + mt * 16 + rh * 8 + gid;
            rv[row * 16 + slot16] = best[mt * 2 + rh];
            ri[row * 16 + slot16] = bidx[mt * 2 + rh];
        }
    __syncthreads();
    if (tid < 128) {
        float bv = rv[tid * 16];
        int   bi = ri[tid * 16];
        #pragma unroll
        for (int s = 1; s < 16; s++) {
            float v = rv[tid * 16 + s];
            int   i = ri[tid * 16 + s];
            if (v < bv || (v == bv && i < bi)) { bv = v; bi = i; }
        }
        g_rbv[ntile * NQ + qt * 128 + tid] = bv;
        g_rbi[ntile * NQ + qt * 128 + tid] = bi;
    }
}

// ---------------------------------------------------------------------------
// k_gather: warp per query row; resolve index, output, loss, histogram.
// ---------------------------------------------------------------------------
__global__ void k_gather(const float* __restrict__ X, const float* __restrict__ E,
                         float* __restrict__ out) {
    const int w = threadIdx.x >> 5;
    const int lane = threadIdx.x & 31;
    const int n = blockIdx.x * 8 + w;
    const int fs = g_flagslot[n];
    int idx;
    if (fs >= 0) {
        float v = g_rbv[lane * NQ + fs];
        int   i = g_rbi[lane * NQ + fs];
        #pragma unroll
        for (int off = 16; off > 0; off >>= 1) {
            float ov = __shfl_down_sync(0xffffffffu, v, off);
            int   oi = __shfl_down_sync(0xffffffffu, i, off);
            if (ov < v || (ov == v && oi < i)) { v = ov; i = oi; }
        }
        idx = __shfl_sync(0xffffffffu, i, 0);
    } else {
        idx = g_outidx[n];
    }

    const float4* qe = (const float4*)(E + (size_t)idx * DIM);
    const float4* xr = (const float4*)(X + (size_t)n * DIM);
    float4* o = (float4*)(out + (size_t)n * DIM);
    float s = 0.f;
    #pragma unroll
    for (int h = 0; h < 2; h++) {
        int j = lane + h * 32;
        float4 q = qe[j], x = xr[j];
        float dx = q.x - x.x, dy = q.y - x.y, dz = q.z - x.z, dw = q.w - x.w;
        float4 r;
        r.x = x.x + dx; r.y = x.y + dy; r.z = x.z + dz; r.w = x.w + dw;
        o[j] = r;
        s += dx * dx + dy * dy + dz * dz + dw * dw;
    }
    #pragma unroll
    for (int off = 16; off > 0; off >>= 1)
        s += __shfl_down_sync(0xffffffffu, s, off);
    if (lane == 0) {
        g_partial[n] = s;
        atomicAdd(&g_counts[idx], 1);
    }
}

// ---------------------------------------------------------------------------
// k_final: deterministic loss + perplexity, warp-shfl reductions.
// ---------------------------------------------------------------------------
__global__ void k_final(float* __restrict__ out, int out_size) {
    __shared__ float wsum[32], wh[32];
    const int t = threadIdx.x;
    const int lane = t & 31;
    const int w = t >> 5;

    float s = 0.f;
    for (int i = t; i < NQ; i += 1024) s += g_partial[i];
    float h = 0.f;
    for (int i = t; i < NC; i += 1024) {
        float p = (float)g_counts[i] * (1.0f / (float)NQ);
        h += p * logf(p + 1e-10f);
    }
    #pragma unroll
    for (int off = 16; off > 0; off >>= 1) {
        s += __shfl_down_sync(0xffffffffu, s, off);
        h += __shfl_down_sync(0xffffffffu, h, off);
    }
    if (lane == 0) { wsum[w] = s; wh[w] = h; }
    __syncthreads();
    if (w == 0) {
        s = wsum[lane];
        h = wh[lane];
        #pragma unroll
        for (int off = 16; off > 0; off >>= 1) {
            s += __shfl_down_sync(0xffffffffu, s, off);
            h += __shfl_down_sync(0xffffffffu, h, off);
        }
        if (lane == 0) {
            float mean_sq = s / (float)((size_t)NQ * DIM);
            float loss = mean_sq + 0.25f * mean_sq;
            float perplexity = expf(-h);
            if (out_size >= NQ * DIM + 2) {
                out[(size_t)NQ * DIM]     = loss;
                out[(size_t)NQ * DIM + 1] = perplexity;
            }
        }
    }
}

// ---------------------------------------------------------------------------
extern "C" void kernel_launch(void* const* d_in, const int* in_sizes, int n_in,
                              void* d_out, int out_size) {
    const float* X = (const float*)d_in[0];   // [32,256,256] -> [8192,256]
    const float* E = (const float*)d_in[1];   // [8192,256]
    float* out = (float*)d_out;

    cudaFuncSetAttribute(k_gemm, cudaFuncAttributeMaxDynamicSharedMemorySize, SC_SMEM);
    cudaFuncSetAttribute(k_rescore, cudaFuncAttributeMaxDynamicSharedMemorySize, RS_SMEM);

    k_split<<<dim3(256, 2), 256>>>(X, E);
    k_gemm<<<dim3(64, 2), 256, SC_SMEM>>>(X);
    k_flag<<<32, 256>>>();
    k_rescore<<<dim3(64, 32), 256, RS_SMEM>>>(X);
    k_gather<<<1024, 256>>>(X, E, out);
    k_final<<<1, 1024>>>(out, out_size);
}

// round 17
// speedup vs baseline: 1.8548x; 1.0694x over previous
#include <cuda_runtime.h>
#include <cuda_fp16.h>
#include <math.h>
#include <stdint.h>

#define NQ 8192
#define NC 8192
#define DIM 256

// Screen image (hi only): per (ntile 0..31, kchunk 0..7) 1024 uint4 (16KB).
// uint4 at [n*4 + (s ^ ((n>>1)&3))] comps c: H2 of k_local = 2s + 8c.
__device__ uint4 g_ehi_img[32 * 8 * 1024];     // 4 MB
// Rescore image (hi+lo): per (ntile, kchunk) 2048 uint4 (32KB).
__device__ uint4 g_esplit[32 * 8 * 2048];      // 8 MB
__device__ float g_enorm[NC];
__device__ int   g_counts[NC];
__device__ float g_partial[NQ];
__device__ float g_sbv[4 * NQ];                // screen per-strip best
__device__ float g_ssv[4 * NQ];                // screen per-strip second
__device__ int   g_sbi[4 * NQ];
__device__ int   g_outidx[NQ];
__device__ float g_xn2[NQ];
__device__ float g_xl2[NQ];
__device__ int   g_maxEl2 = 0;
__device__ int   g_flagq[NQ];
__device__ int   g_flagslot[NQ];
__device__ int   g_flagcount;
__device__ float g_rbv[32 * NQ];
__device__ int   g_rbi[32 * NQ];

#define SC_ES_U4 4096                          // screen: X img 4096 u4 (64KB)
#define SC_STAGE_U4 512                        // 8KB per stage (128 codes x k32)
#define SC_SMEM ((4096 + 3 * 512) * 16)        // 90112 B -> 2 CTAs/SM
#define RS_ES_U4 8192
#define RS_STAGE_U4 2048
#define RS_SMEM ((8192 + 3 * 2048) * 16)       // 229376 B

// ---------------------------------------------------------------------------
__device__ __forceinline__ void mma16(float* c, uint32_t a0, uint32_t a1,
                                      uint32_t a2, uint32_t a3,
                                      uint32_t b0, uint32_t b1) {
    asm volatile(
        "mma.sync.aligned.m16n8k16.row.col.f32.f16.f16.f32 "
        "{%0,%1,%2,%3}, {%4,%5,%6,%7}, {%8,%9}, {%0,%1,%2,%3};"
        : "+f"(c[0]), "+f"(c[1]), "+f"(c[2]), "+f"(c[3])
        : "r"(a0), "r"(a1), "r"(a2), "r"(a3), "r"(b0), "r"(b1));
}

__device__ __forceinline__ uint32_t pack_h2(float v0, float v1) {
    __half2 h = __halves2half2(__float2half_rn(v0), __float2half_rn(v1));
    return *(uint32_t*)&h;
}
__device__ __forceinline__ void split_h2(float v0, float v1,
                                         uint32_t& hi2, uint32_t& lo2) {
    __half h0 = __float2half_rn(v0);
    __half h1 = __float2half_rn(v1);
    __half l0 = __float2half_rn(v0 - __half2float(h0));
    __half l1 = __float2half_rn(v1 - __half2float(h1));
    __half2 hh = __halves2half2(h0, h1);
    __half2 ll = __halves2half2(l0, l1);
    hi2 = *(uint32_t*)&hh;
    lo2 = *(uint32_t*)&ll;
}
__device__ __forceinline__ void split_acc(float v0, float v1,
                                          uint32_t& hi2, uint32_t& lo2, float& lacc) {
    __half h0 = __float2half_rn(v0);
    __half h1 = __float2half_rn(v1);
    float l0 = v0 - __half2float(h0);
    float l1 = v1 - __half2float(h1);
    lacc += l0 * l0 + l1 * l1;
    __half2 hh = __halves2half2(h0, h1);
    __half2 ll = __halves2half2(__float2half_rn(l0), __float2half_rn(l1));
    hi2 = *(uint32_t*)&hh;
    lo2 = *(uint32_t*)&ll;
}
__device__ __forceinline__ void cp16(uint32_t daddr, const void* src) {
    asm volatile("cp.async.cg.shared.global [%0], [%1], 16;" :: "r"(daddr), "l"(src));
}
__device__ __forceinline__ uint32_t smem_u32(const void* p) {
    uint32_t a;
    asm("{ .reg .u64 t; cvta.to.shared.u64 t, %1; cvt.u32.u64 %0, t; }" : "=r"(a) : "l"(p));
    return a;
}

// ---------------------------------------------------------------------------
// k_split: grid (256, 2) x 256. Warp-per-row (4 rows/warp), shfl reduce.
// ---------------------------------------------------------------------------
__global__ void k_split(const float* __restrict__ X, const float* __restrict__ E) {
    const int t = threadIdx.x;
    const int lane = t & 31;
    const int w = t >> 5;
    const int row0 = blockIdx.x * 32 + w * 4;
    const bool isE = (blockIdx.y == 0);
    const float* src = isE ? E : X;

    if (!isE) {
        if (t < 32) g_counts[blockIdx.x * 32 + t] = 0;
        if (blockIdx.x == 0 && t == 0) g_flagcount = 0;
    }

    #pragma unroll
    for (int rr = 0; rr < 4; rr++) {
        const int r = row0 + rr;
        const float4* p = (const float4*)(src + (size_t)r * DIM);
        float4 a = p[2 * lane];
        float4 b = p[2 * lane + 1];
        float vn = a.x * a.x + a.y * a.y + a.z * a.z + a.w * a.w +
                   b.x * b.x + b.y * b.y + b.z * b.z + b.w * b.w;
        float ln = 0.f;
        uint32_t h2[4], l2[4];
        split_acc(a.x, a.y, h2[0], l2[0], ln);
        split_acc(a.z, a.w, h2[1], l2[1], ln);
        split_acc(b.x, b.y, h2[2], l2[2], ln);
        split_acc(b.z, b.w, h2[3], l2[3], ln);

        if (isE) {
            const int n = r & 255;
            const int ntg = r >> 8;
            #pragma unroll
            for (int i = 0; i < 4; i++) {
                const int P = 4 * lane + i;
                const int kc = P >> 4;
                const int pp16 = P & 15;
                uint32_t* ds = (uint32_t*)&g_ehi_img[(ntg * 8 + kc) * 1024 +
                                n * 4 + ((pp16 & 3) ^ ((n >> 1) & 3))];
                ds[pp16 >> 2] = h2[i];
                const int g16 = (P >> 3) & 1;
                const int pp8 = P & 7;
                uint32_t* dr = (uint32_t*)&g_esplit[(ntg * 8 + kc) * 2048 +
                                n * 8 + ((g16 * 4 + (pp8 & 3)) ^ ((n & 1) << 2))];
                dr[(pp8 >> 2) * 2]     = h2[i];
                dr[(pp8 >> 2) * 2 + 1] = l2[i];
            }
        }
        #pragma unroll
        for (int off = 16; off > 0; off >>= 1) {
            vn += __shfl_down_sync(0xffffffffu, vn, off);
            ln += __shfl_down_sync(0xffffffffu, ln, off);
        }
        if (lane == 0) {
            if (isE) {
                g_enorm[r] = vn;
                atomicMax(&g_maxEl2, __float_as_int(ln));
            } else {
                g_xn2[r] = vn;
                g_xl2[r] = ln;
            }
        }
    }
}

// ---------------------------------------------------------------------------
// k_gemm: 1-pass fp16 screen + fused top-2. Grid (64 q-tiles, 4 strips),
// 256 threads, 2 CTAs/SM. CTA tile 128q x 2048n; 8 warps = 2m x 4n (64x32).
// ---------------------------------------------------------------------------
__global__ __launch_bounds__(256, 2) void k_gemm(const float* __restrict__ X) {
    extern __shared__ uint4 smem_u4[];

    const int tid   = threadIdx.x;
    const int lane  = tid & 31;
    const int wid   = tid >> 5;
    const int warpm = wid & 1;            // 0..1, 64 rows
    const int warpn = wid >> 1;           // 0..3, 32 cols
    const int gid   = lane >> 2;
    const int tig   = lane & 3;
    const int q0    = blockIdx.x * 128;
    const int strip = blockIdx.y;         // 0..3, 2048 codes

    const uint32_t es_base = smem_u32(smem_u4 + SC_ES_U4);
    // source for chunk cc (ct = cc>>3, kc = cc&7): 512 u4
    const uint4* img0 = g_ehi_img + (size_t)(strip * 8) * 8 * 1024;

    #pragma unroll
    for (int j = 0; j < 2; j++)
        cp16(es_base + (uint32_t)(tid + j * 256) * 16,
             img0 + tid + j * 256);                           // cc=0: ct0,kc0,half0
    asm volatile("cp.async.commit_group;" ::: "memory");
    #pragma unroll
    for (int j = 0; j < 2; j++)
        cp16(es_base + (uint32_t)(SC_STAGE_U4 + tid + j * 256) * 16,
             img0 + 1024 + tid + j * 256);                    // cc=1: ct0,kc1,half0
    asm volatile("cp.async.commit_group;" ::: "memory");

    // X tile -> hi-fp16 image
    #pragma unroll
    for (int i = 0; i < 32; i++) {
        int idx = tid + i * 256;
        int r = idx >> 6;
        int j = idx & 63;
        float4 v = *(const float4*)(X + (size_t)(q0 + r) * DIM + j * 4);
        uint32_t h2a = pack_h2(v.x, v.y);
        uint32_t h2b = pack_h2(v.z, v.w);
        #pragma unroll
        for (int pp = 0; pp < 2; pp++) {
            int P = 2 * j + pp;
            int kc = P >> 4, p = P & 15, s = p & 3, c = p >> 2;
            uint32_t* d =
                (uint32_t*)&smem_u4[kc * 512 + r * 4 + (s ^ ((r >> 1) & 3))];
            d[c] = pp ? h2b : h2a;
        }
    }

    float bestv[8], secv[8];
    int   besti[8];
    #pragma unroll
    for (int i = 0; i < 8; i++) { bestv[i] = INFINITY; secv[i] = INFINITY; besti[i] = 0; }

    const int cbase0 = strip * 2048;

    for (int ct = 0; ct < 16; ct++) {     // 128-code tiles
        float c[4][4][4];
        #pragma unroll
        for (int mt = 0; mt < 4; mt++)
            #pragma unroll
            for (int nt = 0; nt < 4; nt++)
                #pragma unroll
                for (int r = 0; r < 4; r++) c[mt][nt][r] = 0.f;

        for (int kc = 0; kc < 8; kc++) {
            const int cc = ct * 8 + kc;
            asm volatile("cp.async.wait_group 1;" ::: "memory");
            __syncthreads();

            if (cc + 2 < 128) {
                const int nc = cc + 2;
                const int nct = nc >> 3, nkc = nc & 7;
                const uint4* src = img0 + (size_t)((nct >> 1) * 8 + nkc) * 1024
                                        + (nct & 1) * 512;
                const uint32_t db = es_base + (uint32_t)((nc % 3) * SC_STAGE_U4) * 16;
                #pragma unroll
                for (int j = 0; j < 2; j++)
                    cp16(db + (uint32_t)(tid + j * 256) * 16, src + tid + j * 256);
            }
            asm volatile("cp.async.commit_group;" ::: "memory");

            const uint4* EsB = smem_u4 + SC_ES_U4 + (cc % 3) * SC_STAGE_U4;
            uint4 A0[4], A1[4];
            #pragma unroll
            for (int mt = 0; mt < 4; mt++) {
                const int r = warpm * 64 + mt * 16 + gid;
                const int sw = tig ^ ((r >> 1) & 3);
                A0[mt] = smem_u4[kc * 512 + r * 4 + sw];
                A1[mt] = smem_u4[kc * 512 + (r + 8) * 4 + sw];
            }
            #pragma unroll
            for (int nt = 0; nt < 4; nt++) {
                const int n = warpn * 32 + nt * 8 + gid;   // local 0..127
                uint4 B = EsB[n * 4 + (tig ^ ((n >> 1) & 3))];
                #pragma unroll
                for (int mt = 0; mt < 4; mt++) {
                    mma16(c[mt][nt], A0[mt].x, A1[mt].x, A0[mt].y, A1[mt].y, B.x, B.y);
                    mma16(c[mt][nt], A0[mt].z, A1[mt].z, A0[mt].w, A1[mt].w, B.z, B.w);
                }
            }
        }

        const int cb = cbase0 + ct * 128 + warpn * 32;
        #pragma unroll
        for (int nt = 0; nt < 4; nt++) {
            const int col0 = cb + nt * 8 + tig * 2;
            const float en0 = __ldg(&g_enorm[col0]);
            const float en1 = __ldg(&g_enorm[col0 + 1]);
            #pragma unroll
            for (int mt = 0; mt < 4; mt++) {
                #pragma unroll
                for (int rh = 0; rh < 2; rh++) {
                    const int sl = mt * 2 + rh;
                    float d0 = fmaf(-2.f, c[mt][nt][rh * 2 + 0], en0);
                    float d1 = fmaf(-2.f, c[mt][nt][rh * 2 + 1], en1);
                    if (d0 < secv[sl]) {
                        if (d0 < bestv[sl]) { secv[sl] = bestv[sl]; bestv[sl] = d0; besti[sl] = col0; }
                        else secv[sl] = d0;
                    }
                    if (d1 < secv[sl]) {
                        if (d1 < bestv[sl]) { secv[sl] = bestv[sl]; bestv[sl] = d1; besti[sl] = col0 + 1; }
                        else secv[sl] = d1;
                    }
                }
            }
        }
    }

    // cross-thread top-2 reduce: 16 contributors per query row (24KB in stages)
    __syncthreads();
    float* rv = (float*)(smem_u4 + SC_ES_U4);        // 2048
    float* sv = rv + 2048;                           // 2048
    int*   ri = (int*)(sv + 2048);                   // 2048
    const int slot16 = warpn * 4 + tig;
    #pragma unroll
    for (int mt = 0; mt < 4; mt++)
        #pragma unroll
        for (int rh = 0; rh < 2; rh++) {
            const int row = warpm * 64 + mt * 16 + rh * 8 + gid;
            rv[row * 16 + slot16] = bestv[mt * 2 + rh];
            sv[row * 16 + slot16] = secv[mt * 2 + rh];
            ri[row * 16 + slot16] = besti[mt * 2 + rh];
        }
    __syncthreads();
    if (tid < 128) {
        float B = rv[tid * 16], S = sv[tid * 16];
        int   I = ri[tid * 16];
        #pragma unroll
        for (int s = 1; s < 16; s++) {
            float b = rv[tid * 16 + s], s2 = sv[tid * 16 + s];
            int   i = ri[tid * 16 + s];
            float newS = fminf(fmaxf(B, b), fminf(S, s2));
            if (b < B || (b == B && i < I)) { B = b; I = i; }
            S = newS;
        }
        g_sbv[strip * NQ + q0 + tid] = B;
        g_ssv[strip * NQ + q0 + tid] = S;
        g_sbi[strip * NQ + q0 + tid] = I;
    }
}

// ---------------------------------------------------------------------------
// k_flag: combine 4 strips; sound certainty test.
// ---------------------------------------------------------------------------
__global__ void k_flag() {
    const int n = blockIdx.x * 256 + threadIdx.x;
    float gb = INFINITY;
    int gbi = 0x7fffffff;
    #pragma unroll
    for (int s = 0; s < 4; s++) {
        float b = g_sbv[s * NQ + n];
        int   i = g_sbi[s * NQ + n];
        if (b < gb || (b == gb && i < gbi)) { gb = b; gbi = i; }
    }
    float gs = INFINITY;
    #pragma unroll
    for (int s = 0; s < 4; s++) {
        gs = fminf(gs, g_ssv[s * NQ + n]);
        float b = g_sbv[s * NQ + n];
        if (g_sbi[s * NQ + n] != gbi) gs = fminf(gs, b);
    }
    g_outidx[n] = gbi;

    const float maxEl = sqrtf(__int_as_float(g_maxEl2)) * 1.0001f;
    const float xn = sqrtf(g_xn2[n]);
    const float xl = sqrtf(g_xl2[n]) * 1.0001f;
    const float doterr = xl * (1.0f + maxEl + 1e-5f) + (xn + xl) * maxEl + 3e-4f;
    if (gs - gb <= 4.f * doterr) {
        int s = atomicAdd(&g_flagcount, 1);
        g_flagq[s] = n;
        g_flagslot[n] = s;
    } else {
        g_flagslot[n] = -1;
    }
}

// ---------------------------------------------------------------------------
// k_rescore: exact 3-pass fp16-split GEMM, code-parallel (validated, unchanged).
// ---------------------------------------------------------------------------
__global__ __launch_bounds__(256, 1) void k_rescore(const float* __restrict__ X) {
    const int nf = g_flagcount;
    const int qt = blockIdx.x;
    if (qt * 128 >= nf) return;

    extern __shared__ uint4 smem_u4[];
    const int tid   = threadIdx.x;
    const int lane  = tid & 31;
    const int wid   = tid >> 5;
    const int warpm = wid & 1;
    const int warpn = wid >> 1;
    const int gid   = lane >> 2;
    const int tig   = lane & 3;
    const int ntile = blockIdx.y;
    const int ro    = gid & 1;

    const uint32_t es_base = smem_u32(smem_u4 + RS_ES_U4);
    const uint4* esrc0 = g_esplit + (size_t)ntile * 8 * 2048;

    #pragma unroll
    for (int j = 0; j < 8; j++)
        cp16(es_base + (uint32_t)(tid + j * 256) * 16, esrc0 + tid + j * 256);
    asm volatile("cp.async.commit_group;" ::: "memory");
    #pragma unroll
    for (int j = 0; j < 8; j++)
        cp16(es_base + (uint32_t)(RS_STAGE_U4 + tid + j * 256) * 16,
             esrc0 + 2048 + tid + j * 256);
    asm volatile("cp.async.commit_group;" ::: "memory");

    #pragma unroll
    for (int i = 0; i < 32; i++) {
        int idx = tid + i * 256;
        int r = idx >> 6;
        int j = idx & 63;
        int slot = qt * 128 + r;
        int qrow = g_flagq[min(slot, nf - 1)];
        float4 v = *(const float4*)(X + (size_t)qrow * DIM + j * 4);
        int g16 = j >> 2;
        int p0  = (j & 3) * 2;
        int tg0 = p0 & 3;
        int h8  = p0 >> 2;
        int rsw = (r & 1) << 2;
        uint32_t h2a, l2a, h2b, l2b;
        split_h2(v.x, v.y, h2a, l2a);
        split_h2(v.z, v.w, h2b, l2b);
        uint32_t* d0 = (uint32_t*)&smem_u4[r * 64 + ((g16 * 4 + tg0) ^ rsw)];
        uint32_t* d1 = (uint32_t*)&smem_u4[r * 64 + ((g16 * 4 + tg0 + 1) ^ rsw)];
        d0[h8 * 2] = h2a;  d0[h8 * 2 + 1] = l2a;
        d1[h8 * 2] = h2b;  d1[h8 * 2 + 1] = l2b;
    }

    float best[8];
    int   bidx[8];
    #pragma unroll
    for (int i = 0; i < 8; i++) { best[i] = INFINITY; bidx[i] = 0; }

    float c[4][8][4];
    #pragma unroll
    for (int mt = 0; mt < 4; mt++)
        #pragma unroll
        for (int nt = 0; nt < 8; nt++)
            #pragma unroll
            for (int r = 0; r < 4; r++) c[mt][nt][r] = 0.f;

    for (int kc = 0; kc < 8; kc++) {
        asm volatile("cp.async.wait_group 1;" ::: "memory");
        __syncthreads();

        if (kc + 2 < 8) {
            const uint32_t db = es_base + (uint32_t)(((kc + 2) % 3) * RS_STAGE_U4) * 16;
            const uint4* src = esrc0 + (size_t)(kc + 2) * 2048;
            #pragma unroll
            for (int j = 0; j < 8; j++)
                cp16(db + (uint32_t)(tid + j * 256) * 16, src + tid + j * 256);
        }
        asm volatile("cp.async.commit_group;" ::: "memory");

        const uint4* EsB = smem_u4 + RS_ES_U4 + (kc % 3) * RS_STAGE_U4;
        #pragma unroll
        for (int gg = 0; gg < 2; gg++) {
            uint4 A0[4], A1[4];
            const int sA = ((2 * kc + gg) * 4 + tig) ^ (ro << 2);
            #pragma unroll
            for (int mt = 0; mt < 4; mt++) {
                const int r = warpm * 64 + mt * 16 + gid;
                A0[mt] = smem_u4[r * 64 + sA];
                A1[mt] = smem_u4[(r + 8) * 64 + sA];
            }
            const int sB = (gg * 4 + tig) ^ (ro << 2);
            #pragma unroll
            for (int nt = 0; nt < 8; nt++) {
                const int n = warpn * 64 + nt * 8 + gid;
                uint4 B = EsB[n * 8 + sB];
                #pragma unroll
                for (int mt = 0; mt < 4; mt++) {
                    mma16(c[mt][nt], A0[mt].x, A1[mt].x, A0[mt].z, A1[mt].z, B.x, B.z);
                    mma16(c[mt][nt], A0[mt].x, A1[mt].x, A0[mt].z, A1[mt].z, B.y, B.w);
                    mma16(c[mt][nt], A0[mt].y, A1[mt].y, A0[mt].w, A1[mt].w, B.x, B.z);
                }
            }
        }
    }

    const int cb = ntile * 256 + warpn * 64;
    #pragma unroll
    for (int nt = 0; nt < 8; nt++) {
        const int col0 = cb + nt * 8 + tig * 2;
        const float en0 = __ldg(&g_enorm[col0]);
        const float en1 = __ldg(&g_enorm[col0 + 1]);
        #pragma unroll
        for (int mt = 0; mt < 4; mt++) {
            float d;
            d = fmaf(-2.f, c[mt][nt][0], en0);
            if (d < best[mt * 2 + 0]) { best[mt * 2 + 0] = d; bidx[mt * 2 + 0] = col0; }
            d = fmaf(-2.f, c[mt][nt][1], en1);
            if (d < best[mt * 2 + 0]) { best[mt * 2 + 0] = d; bidx[mt * 2 + 0] = col0 + 1; }
            d = fmaf(-2.f, c[mt][nt][2], en0);
            if (d < best[mt * 2 + 1]) { best[mt * 2 + 1] = d; bidx[mt * 2 + 1] = col0; }
            d = fmaf(-2.f, c[mt][nt][3], en1);
            if (d < best[mt * 2 + 1]) { best[mt * 2 + 1] = d; bidx[mt * 2 + 1] = col0 + 1; }
        }
    }

    __syncthreads();
    float* rv = (float*)(smem_u4 + RS_ES_U4);
    int*   ri = (int*)(rv + 2048);
    const int slot16 = warpn * 4 + tig;
    #pragma unroll
    for (int mt = 0; mt < 4; mt++)
        #pragma unroll
        for (int rh = 0; rh < 2; rh++) {
            const int row = warpm * 64 + mt * 16 + rh * 8 + gid;
            rv[row * 16 + slot16] = best[mt * 2 + rh];
            ri[row * 16 + slot16] = bidx[mt * 2 + rh];
        }
    __syncthreads();
    if (tid < 128) {
        float bv = rv[tid * 16];
        int   bi = ri[tid * 16];
        #pragma unroll
        for (int s = 1; s < 16; s++) {
            float v = rv[tid * 16 + s];
            int   i = ri[tid * 16 + s];
            if (v < bv || (v == bv && i < bi)) { bv = v; bi = i; }
        }
        g_rbv[ntile * NQ + qt * 128 + tid] = bv;
        g_rbi[ntile * NQ + qt * 128 + tid] = bi;
    }
}

// ---------------------------------------------------------------------------
// k_gather: warp per query row; resolve index, output, loss, histogram.
// ---------------------------------------------------------------------------
__global__ void k_gather(const float* __restrict__ X, const float* __restrict__ E,
                         float* __restrict__ out) {
    const int w = threadIdx.x >> 5;
    const int lane = threadIdx.x & 31;
    const int n = blockIdx.x * 8 + w;
    const int fs = g_flagslot[n];
    int idx;
    if (fs >= 0) {
        float v = g_rbv[lane * NQ + fs];
        int   i = g_rbi[lane * NQ + fs];
        #pragma unroll
        for (int off = 16; off > 0; off >>= 1) {
            float ov = __shfl_down_sync(0xffffffffu, v, off);
            int   oi = __shfl_down_sync(0xffffffffu, i, off);
            if (ov < v || (ov == v && oi < i)) { v = ov; i = oi; }
        }
        idx = __shfl_sync(0xffffffffu, i, 0);
    } else {
        idx = g_outidx[n];
    }

    const float4* qe = (const float4*)(E + (size_t)idx * DIM);
    const float4* xr = (const float4*)(X + (size_t)n * DIM);
    float4* o = (float4*)(out + (size_t)n * DIM);
    float s = 0.f;
    #pragma unroll
    for (int h = 0; h < 2; h++) {
        int j = lane + h * 32;
        float4 q = qe[j], x = xr[j];
        float dx = q.x - x.x, dy = q.y - x.y, dz = q.z - x.z, dw = q.w - x.w;
        float4 r;
        r.x = x.x + dx; r.y = x.y + dy; r.z = x.z + dz; r.w = x.w + dw;
        o[j] = r;
        s += dx * dx + dy * dy + dz * dz + dw * dw;
    }
    #pragma unroll
    for (int off = 16; off > 0; off >>= 1)
        s += __shfl_down_sync(0xffffffffu, s, off);
    if (lane == 0) {
        g_partial[n] = s;
        atomicAdd(&g_counts[idx], 1);
    }
}

// ---------------------------------------------------------------------------
// k_final: deterministic loss + perplexity, warp-shfl reductions.
// ---------------------------------------------------------------------------
__global__ void k_final(float* __restrict__ out, int out_size) {
    __shared__ float wsum[32], wh[32];
    const int t = threadIdx.x;
    const int lane = t & 31;
    const int w = t >> 5;

    float s = 0.f;
    for (int i = t; i < NQ; i += 1024) s += g_partial[i];
    float h = 0.f;
    for (int i = t; i < NC; i += 1024) {
        float p = (float)g_counts[i] * (1.0f / (float)NQ);
        h += p * logf(p + 1e-10f);
    }
    #pragma unroll
    for (int off = 16; off > 0; off >>= 1) {
        s += __shfl_down_sync(0xffffffffu, s, off);
        h += __shfl_down_sync(0xffffffffu, h, off);
    }
    if (lane == 0) { wsum[w] = s; wh[w] = h; }
    __syncthreads();
    if (w == 0) {
        s = wsum[lane];
        h = wh[lane];
        #pragma unroll
        for (int off = 16; off > 0; off >>= 1) {
            s += __shfl_down_sync(0xffffffffu, s, off);
            h += __shfl_down_sync(0xffffffffu, h, off);
        }
        if (lane == 0) {
            float mean_sq = s / (float)((size_t)NQ * DIM);
            float loss = mean_sq + 0.25f * mean_sq;
            float perplexity = expf(-h);
            if (out_size >= NQ * DIM + 2) {
                out[(size_t)NQ * DIM]     = loss;
                out[(size_t)NQ * DIM + 1] = perplexity;
            }
        }
    }
}

// ---------------------------------------------------------------------------
extern "C" void kernel_launch(void* const* d_in, const int* in_sizes, int n_in,
                              void* d_out, int out_size) {
    const float* X = (const float*)d_in[0];   // [32,256,256] -> [8192,256]
    const float* E = (const float*)d_in[1];   // [8192,256]
    float* out = (float*)d_out;

    cudaFuncSetAttribute(k_gemm, cudaFuncAttributeMaxDynamicSharedMemorySize, SC_SMEM);
    cudaFuncSetAttribute(k_rescore, cudaFuncAttributeMaxDynamicSharedMemorySize, RS_SMEM);

    k_split<<<dim3(256, 2), 256>>>(X, E);
    k_gemm<<<dim3(64, 4), 256, SC_SMEM>>>(X);
    k_flag<<<32, 256>>>();
    k_rescore<<<dim3(64, 32), 256, RS_SMEM>>>(X);
    k_gather<<<1024, 256>>>(X, E, out);
    k_final<<<1, 1024>>>(out, out_size);
}